// round 4
// baseline (speedup 1.0000x reference)
#include <cuda_runtime.h>
#include <cstdint>

// Problem constants
#define BATCH 8
#define CDIM  128
#define NPOS  2304              // H*W = 48*48
#define TM    128               // CTA tile M (y rows)
#define TN    64                // CTA tile N (x cols)
#define MT_M  (NPOS / TM)       // 18
#define MT_N  (NPOS / TN)       // 36

// ---------------------------------------------------------------------------
// Scratch for squared norms (device globals — no allocation in kernel_launch)
// ---------------------------------------------------------------------------
__device__ float g_sx[BATCH * NPOS];
__device__ float g_sy[BATCH * NPOS];

// ---------------------------------------------------------------------------
// Kernel 1: per-position squared norms   sx[b,n] = sum_c x[b,c,n]^2
// ---------------------------------------------------------------------------
__global__ void pwd_norms_kernel(const float* __restrict__ x,
                                 const float* __restrict__ y) {
    int idx = blockIdx.x * blockDim.x + threadIdx.x;
    if (idx >= BATCH * NPOS) return;
    int b = idx / NPOS;
    int n = idx - b * NPOS;
    const float* xp = x + (size_t)b * CDIM * NPOS + n;
    const float* yp = y + (size_t)b * CDIM * NPOS + n;
    float sx = 0.f, sy = 0.f;
#pragma unroll 8
    for (int c = 0; c < CDIM; c++) {
        float xv = xp[(size_t)c * NPOS];
        float yv = yp[(size_t)c * NPOS];
        sx = fmaf(xv, xv, sx);
        sy = fmaf(yv, yv, sy);
    }
    g_sx[idx] = sx;
    g_sy[idx] = sy;
}

// ---------------------------------------------------------------------------
// tf32 warp MMA helper (sm_80+ PTX — valid under compute_100)
// D(16x8) += A(16x8,row) * B(8x8,col)
// ---------------------------------------------------------------------------
__device__ __forceinline__ void mma_tf32(
    float& d0, float& d1, float& d2, float& d3,
    uint32_t a0, uint32_t a1, uint32_t a2, uint32_t a3,
    uint32_t b0, uint32_t b1)
{
    asm volatile(
        "mma.sync.aligned.m16n8k8.row.col.f32.tf32.tf32.f32 "
        "{%0,%1,%2,%3}, {%4,%5,%6,%7}, {%8,%9}, {%0,%1,%2,%3};"
        : "+f"(d0), "+f"(d1), "+f"(d2), "+f"(d3)
        : "r"(a0), "r"(a1), "r"(a2), "r"(a3), "r"(b0), "r"(b1));
}

__device__ __forceinline__ uint32_t f2tf32(float v) {
    uint32_t r;
    asm("cvt.rna.tf32.f32 %0, %1;" : "=r"(r) : "f"(v));
    return r;
}

// XOR swizzle of the k-index within a 128-word row; conflict-free for both
// the m-contiguous transpose stores and the mma fragment loads.
__device__ __forceinline__ int kswz(int row) {
    return ((row & 7) << 2) ^ ((row >> 3) & 3);
}

// ---------------------------------------------------------------------------
// Kernel 2: tf32 mma.sync GEMM tile + fused epilogue
//   acc[m][n] = y_i . x_j  (i = m0+m row, j = n0+n col)
//   reference: out[b,i,j] = sx[i] + sy[j] - 2 * acc   (crossed norms!)
// ---------------------------------------------------------------------------
__global__ __launch_bounds__(256, 2)
void pwd_gemm_kernel(const float* __restrict__ x,
                     const float* __restrict__ y,
                     float* __restrict__ out) {
    extern __shared__ uint32_t smem[];      // sA[128*128] ++ sB[64*128]
    uint32_t* sA = smem;                    // A: y tile, [m][k']
    uint32_t* sB = smem + TM * CDIM;        // B: x tile, [n][k']
    __shared__ float s_sxRow[TM];           // ||x_i||^2 at ROW positions
    __shared__ float s_syCol[TN];           // ||y_j||^2 at COL positions

    int tid  = threadIdx.x;
    int lane = tid & 31;
    int w    = tid >> 5;
    int qid  = lane >> 2;   // 0..7
    int qtr  = lane & 3;    // 0..3
    int wm   = w & 3;       // warp row  (32 rows each)
    int wn   = w >> 2;      // warp col  0..1 (32 cols each)

    int n0 = blockIdx.x * TN;
    int m0 = blockIdx.y * TM;
    int b  = blockIdx.z;

    // ---- stage tiles (gmem [c][pos] -> smem [pos][k'], cvt to tf32) ----
    const float* yb = y + (size_t)b * CDIM * NPOS + m0;
    const float* xb = x + (size_t)b * CDIM * NPOS + n0;

#pragma unroll 8
    for (int e = tid; e < TM * CDIM; e += 256) {
        int c = e >> 7;         // k
        int m = e & 127;
        sA[m * CDIM + (c ^ kswz(m))] = f2tf32(yb[(size_t)c * NPOS + m]);
    }
#pragma unroll 4
    for (int e = tid; e < TN * CDIM; e += 256) {
        int c = e >> 6;
        int n = e & 63;
        sB[n * CDIM + (c ^ kswz(n))] = f2tf32(xb[(size_t)c * NPOS + n]);
    }
    // Crossed norms per reference: sx indexed by row i, sy indexed by col j.
    if (tid < TM) {
        s_sxRow[tid] = g_sx[b * NPOS + m0 + tid];
    } else if (tid < TM + TN) {
        s_syCol[tid - TM] = g_sy[b * NPOS + n0 + (tid - TM)];
    }
    __syncthreads();

    // ---- precomputed per-thread fragment addressing ----
    // A rows: rA[mi][h] = wm*32 + mi*16 + h*8 + qid
    int aBase[2][2], aSwz[2][2];
#pragma unroll
    for (int mi = 0; mi < 2; mi++)
#pragma unroll
        for (int h = 0; h < 2; h++) {
            int r = wm * 32 + mi * 16 + h * 8 + qid;
            aBase[mi][h] = r * CDIM;
            aSwz[mi][h]  = kswz(r);
        }
    // B rows: n[j] = wn*32 + 8*j + qid
    int bBase[4], bSwz[4];
#pragma unroll
    for (int j = 0; j < 4; j++) {
        int n = wn * 32 + 8 * j + qid;
        bBase[j] = n * CDIM;
        bSwz[j]  = kswz(n);
    }

    float acc[2][4][4];
#pragma unroll
    for (int mi = 0; mi < 2; mi++)
#pragma unroll
        for (int j = 0; j < 4; j++)
#pragma unroll
            for (int r = 0; r < 4; r++) acc[mi][j][r] = 0.f;

    // ---- main loop: 16 k-steps of 8 ----
#pragma unroll
    for (int s = 0; s < 16; s++) {
        int k0 = s * 8 + qtr;
        int k1 = k0 + 4;

        uint32_t af[2][4];
#pragma unroll
        for (int mi = 0; mi < 2; mi++) {
            af[mi][0] = sA[aBase[mi][0] + (k0 ^ aSwz[mi][0])];
            af[mi][1] = sA[aBase[mi][1] + (k0 ^ aSwz[mi][1])];
            af[mi][2] = sA[aBase[mi][0] + (k1 ^ aSwz[mi][0])];
            af[mi][3] = sA[aBase[mi][1] + (k1 ^ aSwz[mi][1])];
        }
#pragma unroll
        for (int j = 0; j < 4; j++) {
            uint32_t b0 = sB[bBase[j] + (k0 ^ bSwz[j])];
            uint32_t b1 = sB[bBase[j] + (k1 ^ bSwz[j])];
#pragma unroll
            for (int mi = 0; mi < 2; mi++) {
                mma_tf32(acc[mi][j][0], acc[mi][j][1], acc[mi][j][2], acc[mi][j][3],
                         af[mi][0], af[mi][1], af[mi][2], af[mi][3], b0, b1);
            }
        }
    }

    // ---- fused epilogue: P = sx[i] + sy[j] - 2*acc, float2 stores ----
#pragma unroll
    for (int mi = 0; mi < 2; mi++) {
#pragma unroll
        for (int h = 0; h < 2; h++) {
            int r = wm * 32 + mi * 16 + h * 8 + qid;
            float sxv = s_sxRow[r];
            size_t rowOff = ((size_t)b * NPOS + m0 + r) * (size_t)NPOS + n0;
#pragma unroll
            for (int j = 0; j < 4; j++) {
                int cb = wn * 32 + 8 * j + 2 * qtr;
                float d0 = acc[mi][j][h * 2 + 0];
                float d1 = acc[mi][j][h * 2 + 1];
                float2 v;
                v.x = s_syCol[cb + 0] + fmaf(-2.f, d0, sxv);
                v.y = s_syCol[cb + 1] + fmaf(-2.f, d1, sxv);
                *reinterpret_cast<float2*>(out + rowOff + cb) = v;
            }
        }
    }
}

// ---------------------------------------------------------------------------
// Launch
// ---------------------------------------------------------------------------
extern "C" void kernel_launch(void* const* d_in, const int* in_sizes, int n_in,
                              void* d_out, int out_size) {
    const float* x = (const float*)d_in[0];
    const float* y = (const float*)d_in[1];
    float* out = (float*)d_out;

    // Kernel 1: squared norms
    int total = BATCH * NPOS;
    pwd_norms_kernel<<<(total + 255) / 256, 256>>>(x, y);

    // Kernel 2: tiled tf32 GEMM + fused epilogue
    int smemBytes = (TM * CDIM + TN * CDIM) * 4;   // 96 KB
    cudaFuncSetAttribute(pwd_gemm_kernel,
                         cudaFuncAttributeMaxDynamicSharedMemorySize, smemBytes);
    dim3 grid(MT_N, MT_M, BATCH);
    pwd_gemm_kernel<<<grid, 256, smemBytes>>>(x, y, out);
}

// round 6
// speedup vs baseline: 1.1854x; 1.1854x over previous
#include <cuda_runtime.h>
#include <cstdint>

// Problem constants
#define BATCH 8
#define CDIM  128
#define NPOS  2304              // H*W = 48*48
#define TM    128               // CTA tile M (y rows)
#define TN    64                // CTA tile N (x cols)
#define MT_M  (NPOS / TM)       // 18
#define MT_N  (NPOS / TN)       // 36
#define LDS_STRIDE 132          // 128 + 4 padding words: (4*r + k) % 32 conflict-free

// ---------------------------------------------------------------------------
// Scratch for squared norms (device globals — no allocation in kernel_launch)
// ---------------------------------------------------------------------------
__device__ float g_sx[BATCH * NPOS];
__device__ float g_sy[BATCH * NPOS];

// ---------------------------------------------------------------------------
// Kernel 1: per-position squared norms   sx[b,n] = sum_c x[b,c,n]^2
// ---------------------------------------------------------------------------
__global__ void pwd_norms_kernel(const float* __restrict__ x,
                                 const float* __restrict__ y) {
    int idx = blockIdx.x * blockDim.x + threadIdx.x;
    if (idx >= BATCH * NPOS) return;
    int b = idx / NPOS;
    int n = idx - b * NPOS;
    const float* xp = x + (size_t)b * CDIM * NPOS + n;
    const float* yp = y + (size_t)b * CDIM * NPOS + n;
    float sx = 0.f, sy = 0.f;
#pragma unroll 8
    for (int c = 0; c < CDIM; c++) {
        float xv = xp[(size_t)c * NPOS];
        float yv = yp[(size_t)c * NPOS];
        sx = fmaf(xv, xv, sx);
        sy = fmaf(yv, yv, sy);
    }
    g_sx[idx] = sx;
    g_sy[idx] = sy;
}

// ---------------------------------------------------------------------------
// tf32 warp MMA helper (sm_80+ PTX — valid under compute_100)
// ---------------------------------------------------------------------------
__device__ __forceinline__ void mma_tf32(
    float& d0, float& d1, float& d2, float& d3,
    uint32_t a0, uint32_t a1, uint32_t a2, uint32_t a3,
    uint32_t b0, uint32_t b1)
{
    asm volatile(
        "mma.sync.aligned.m16n8k8.row.col.f32.tf32.tf32.f32 "
        "{%0,%1,%2,%3}, {%4,%5,%6,%7}, {%8,%9}, {%0,%1,%2,%3};"
        : "+f"(d0), "+f"(d1), "+f"(d2), "+f"(d3)
        : "r"(a0), "r"(a1), "r"(a2), "r"(a3), "r"(b0), "r"(b1));
}

__device__ __forceinline__ uint32_t f2tf32(float v) {
    uint32_t r;
    asm("cvt.rna.tf32.f32 %0, %1;" : "=r"(r) : "f"(v));
    return r;
}

// ---------------------------------------------------------------------------
// Kernel 2: tf32 mma.sync GEMM tile + fused epilogue
//   acc[m][n] = y_i . x_j  (i = m0+m row, j = n0+n col)
//   out[b,i,j] = sx[i] + sy[j] - 2 * acc   (crossed norms per reference)
//
// SMEM: padded stride 132 words. No XOR swizzle: all inner-loop addresses
// fold to [Rbase + imm]. Staging uses an (l&7, l>>3) lane decomposition so
// STS banks = 4*(l&7) + (l>>3) are all distinct.
// ---------------------------------------------------------------------------
__global__ __launch_bounds__(256, 2)
void pwd_gemm_kernel(const float* __restrict__ x,
                     const float* __restrict__ y,
                     float* __restrict__ out) {
    extern __shared__ uint32_t dsm[];
    uint32_t* sA = dsm;                                // 128 * 132 words
    uint32_t* sB = dsm + TM * LDS_STRIDE;              // 64 * 132 words
    float* s_sxRow = (float*)(dsm + (TM + TN) * LDS_STRIDE);   // 128
    float* s_syCol = s_sxRow + TM;                              // 64

    int tid  = threadIdx.x;
    int lane = tid & 31;
    int w    = tid >> 5;
    int qid  = lane >> 2;   // 0..7
    int qtr  = lane & 3;    // 0..3
    int wm   = w & 3;       // warp row (32 rows each)
    int wn   = w >> 2;      // warp col 0..1 (32 cols each)

    int n0 = blockIdx.x * TN;
    int m0 = blockIdx.y * TM;
    int b  = blockIdx.z;

    const float* yb = y + (size_t)b * CDIM * NPOS + m0;
    const float* xb = x + (size_t)b * CDIM * NPOS + n0;

    // ---- stage tiles: gmem [k][pos] -> smem [pos][k], cvt to tf32 ----
    // lane map: pos_lo = tid&7, k_lo = (tid>>3)&3  (conflict-free STS,
    // 4x32B-sector coalesced LDG)
    int plo = tid & 7;
    int klo = (tid >> 3) & 3;
    int w5  = tid >> 5;

#pragma unroll
    for (int i = 0; i < (TM * CDIM) / 256; i++) {     // 64 iters
        int hi = i * 8 + w5;                          // 0..511
        int m  = plo | ((hi >> 5) << 3);              // 0..127
        int k  = klo | ((hi & 31) << 2);              // 0..127
        sA[m * LDS_STRIDE + k] = f2tf32(yb[(size_t)k * NPOS + m]);
    }
#pragma unroll
    for (int i = 0; i < (TN * CDIM) / 256; i++) {     // 32 iters
        int hi = i * 8 + w5;                          // 0..255
        int n  = plo | ((hi >> 5) << 3);              // 0..63
        int k  = klo | ((hi & 31) << 2);              // 0..127
        sB[n * LDS_STRIDE + k] = f2tf32(xb[(size_t)k * NPOS + n]);
    }
    // Crossed norms: sx indexed by row i, sy indexed by col j.
    if (tid < TM) {
        s_sxRow[tid] = g_sx[b * NPOS + m0 + tid];
    } else if (tid < TM + TN) {
        s_syCol[tid - TM] = g_sy[b * NPOS + n0 + (tid - TM)];
    }
    __syncthreads();

    // ---- per-thread base pointers; all further offsets are immediates ----
    const uint32_t* pA = sA + (wm * 32 + qid) * LDS_STRIDE + qtr;
    const uint32_t* pB = sB + (wn * 32 + qid) * LDS_STRIDE + qtr;

    float acc[2][4][4];
#pragma unroll
    for (int mi = 0; mi < 2; mi++)
#pragma unroll
        for (int j = 0; j < 4; j++)
#pragma unroll
            for (int r = 0; r < 4; r++) acc[mi][j][r] = 0.f;

    // ---- main loop: 16 k-steps of 8, zero inner-loop address ALU ----
#pragma unroll
    for (int s = 0; s < 16; s++) {
        uint32_t af[2][4];
#pragma unroll
        for (int mi = 0; mi < 2; mi++) {
            af[mi][0] = pA[(mi * 16 + 0) * LDS_STRIDE + s * 8];
            af[mi][1] = pA[(mi * 16 + 8) * LDS_STRIDE + s * 8];
            af[mi][2] = pA[(mi * 16 + 0) * LDS_STRIDE + s * 8 + 4];
            af[mi][3] = pA[(mi * 16 + 8) * LDS_STRIDE + s * 8 + 4];
        }
#pragma unroll
        for (int j = 0; j < 4; j++) {
            uint32_t b0 = pB[j * 8 * LDS_STRIDE + s * 8];
            uint32_t b1 = pB[j * 8 * LDS_STRIDE + s * 8 + 4];
#pragma unroll
            for (int mi = 0; mi < 2; mi++) {
                mma_tf32(acc[mi][j][0], acc[mi][j][1], acc[mi][j][2], acc[mi][j][3],
                         af[mi][0], af[mi][1], af[mi][2], af[mi][3], b0, b1);
            }
        }
    }

    // ---- fused epilogue: P = sx[i] + sy[j] - 2*acc, float2 stores ----
#pragma unroll
    for (int mi = 0; mi < 2; mi++) {
#pragma unroll
        for (int h = 0; h < 2; h++) {
            int r = wm * 32 + mi * 16 + h * 8 + qid;
            float sxv = s_sxRow[r];
            size_t rowOff = ((size_t)b * NPOS + m0 + r) * (size_t)NPOS + n0;
#pragma unroll
            for (int j = 0; j < 4; j++) {
                int cb = wn * 32 + 8 * j + 2 * qtr;
                float d0 = acc[mi][j][h * 2 + 0];
                float d1 = acc[mi][j][h * 2 + 1];
                float2 v;
                v.x = s_syCol[cb + 0] + fmaf(-2.f, d0, sxv);
                v.y = s_syCol[cb + 1] + fmaf(-2.f, d1, sxv);
                *reinterpret_cast<float2*>(out + rowOff + cb) = v;
            }
        }
    }
}

// ---------------------------------------------------------------------------
// Launch
// ---------------------------------------------------------------------------
extern "C" void kernel_launch(void* const* d_in, const int* in_sizes, int n_in,
                              void* d_out, int out_size) {
    const float* x = (const float*)d_in[0];
    const float* y = (const float*)d_in[1];
    float* out = (float*)d_out;

    // Kernel 1: squared norms
    int total = BATCH * NPOS;
    pwd_norms_kernel<<<(total + 255) / 256, 256>>>(x, y);

    // Kernel 2: tiled tf32 GEMM + fused epilogue
    int smemBytes = ((TM + TN) * LDS_STRIDE + TM + TN) * 4;   // ~101.5 KB
    cudaFuncSetAttribute(pwd_gemm_kernel,
                         cudaFuncAttributeMaxDynamicSharedMemorySize, smemBytes);
    dim3 grid(MT_N, MT_M, BATCH);
    pwd_gemm_kernel<<<grid, 256, smemBytes>>>(x, y, out);
}

// round 9
// speedup vs baseline: 1.5002x; 1.2656x over previous
#include <cuda_runtime.h>
#include <cuda_bf16.h>
#include <cstdint>

// Problem constants
#define BATCH 8
#define CDIM  128
#define NPOS  2304              // H*W = 48*48
#define TM    128               // CTA tile M (y rows)
#define TN    64                // CTA tile N (x cols)
#define MT_M  (NPOS / TM)       // 18
#define MT_N  (NPOS / TN)       // 36
#define SW    68                // SMEM row stride in 32-bit words (64 + 4 pad)

// ---------------------------------------------------------------------------
// Scratch for squared norms (device globals — no allocation in kernel_launch)
// ---------------------------------------------------------------------------
__device__ float g_sx[BATCH * NPOS];
__device__ float g_sy[BATCH * NPOS];

// ---------------------------------------------------------------------------
// Kernel 1: per-position squared norms   sx[b,n] = sum_c x[b,c,n]^2  (fp32 exact)
// ---------------------------------------------------------------------------
__global__ void pwd_norms_kernel(const float* __restrict__ x,
                                 const float* __restrict__ y) {
    int idx = blockIdx.x * blockDim.x + threadIdx.x;
    if (idx >= BATCH * NPOS) return;
    int b = idx / NPOS;
    int n = idx - b * NPOS;
    const float* xp = x + (size_t)b * CDIM * NPOS + n;
    const float* yp = y + (size_t)b * CDIM * NPOS + n;
    float sx = 0.f, sy = 0.f;
#pragma unroll 8
    for (int c = 0; c < CDIM; c++) {
        float xv = xp[(size_t)c * NPOS];
        float yv = yp[(size_t)c * NPOS];
        sx = fmaf(xv, xv, sx);
        sy = fmaf(yv, yv, sy);
    }
    g_sx[idx] = sx;
    g_sy[idx] = sy;
}

// ---------------------------------------------------------------------------
// bf16 warp MMA (sm_80+ PTX): D(16x8,f32) += A(16x16,bf16) * B(16x8,bf16)
// ---------------------------------------------------------------------------
__device__ __forceinline__ void mma_bf16(
    float& d0, float& d1, float& d2, float& d3,
    uint32_t a0, uint32_t a1, uint32_t a2, uint32_t a3,
    uint32_t b0, uint32_t b1)
{
    asm volatile(
        "mma.sync.aligned.m16n8k16.row.col.f32.bf16.bf16.f32 "
        "{%0,%1,%2,%3}, {%4,%5,%6,%7}, {%8,%9}, {%0,%1,%2,%3};"
        : "+f"(d0), "+f"(d1), "+f"(d2), "+f"(d3)
        : "r"(a0), "r"(a1), "r"(a2), "r"(a3), "r"(b0), "r"(b1));
}

__device__ __forceinline__ uint32_t pack_bf16x2(float lo, float hi) {
    __nv_bfloat162 p = __floats2bfloat162_rn(lo, hi);   // .x = lo (lower k)
    return *reinterpret_cast<uint32_t*>(&p);
}

// ---------------------------------------------------------------------------
// Kernel 2: bf16 mma.sync GEMM tile + fused epilogue
//   acc[m][n] = y_i . x_j   (i = m0+m row, j = n0+n col)
//   out[b,i,j] = sx[i] + sy[j] - 2 * acc   (crossed norms per reference)
//
// SMEM rows hold 64 bf16x2 words (k-pairs), stride SW=68 words.
// Fragment LDS bank = (4*qid + qtr) mod 32 -> conflict-free.
// Staging STS bank  = (4*plo + klo) mod 32 -> conflict-free.
// ---------------------------------------------------------------------------
__global__ __launch_bounds__(256, 2)
void pwd_gemm_kernel(const float* __restrict__ x,
                     const float* __restrict__ y,
                     float* __restrict__ out) {
    extern __shared__ uint32_t dsm[];
    uint32_t* sA = dsm;                            // 128 * 68 words
    uint32_t* sB = dsm + TM * SW;                  // 64 * 68 words
    float* s_sxRow = (float*)(dsm + (TM + TN) * SW);   // 128 floats
    float* s_syCol = s_sxRow + TM;                     // 64 floats

    int tid  = threadIdx.x;
    int lane = tid & 31;
    int w    = tid >> 5;
    int qid  = lane >> 2;   // 0..7
    int qtr  = lane & 3;    // 0..3
    int wm   = w & 3;       // warp row (32 rows each)
    int wn   = w >> 2;      // warp col 0..1 (32 cols each)

    int n0 = blockIdx.x * TN;
    int m0 = blockIdx.y * TM;
    int b  = blockIdx.z;

    const float* yb = y + (size_t)b * CDIM * NPOS + m0;
    const float* xb = x + (size_t)b * CDIM * NPOS + n0;

    // ---- stage tiles: gmem [k][pos] fp32 -> smem [pos][kp] bf16x2 ----
    // lane map: plo = tid&7 (pos low), klo = (tid>>3)&3 (k-pair low)
    int plo = tid & 7;
    int klo = (tid >> 3) & 3;
    int w5  = tid >> 5;

#pragma unroll
    for (int i = 0; i < (TM * (CDIM / 2)) / 256; i++) {   // 32 iters
        int hi  = i * 8 + w5;                             // 0..255
        int m   = plo | ((hi >> 4) << 3);                 // 0..127
        int kp  = klo | ((hi & 15) << 2);                 // 0..63
        float f0 = yb[(size_t)(2 * kp) * NPOS + m];
        float f1 = yb[(size_t)(2 * kp + 1) * NPOS + m];
        sA[m * SW + kp] = pack_bf16x2(f0, f1);
    }
#pragma unroll
    for (int i = 0; i < (TN * (CDIM / 2)) / 256; i++) {   // 16 iters
        int hi  = i * 8 + w5;                             // 0..127
        int n   = plo | ((hi >> 4) << 3);                 // 0..63
        int kp  = klo | ((hi & 15) << 2);                 // 0..63
        float f0 = xb[(size_t)(2 * kp) * NPOS + n];
        float f1 = xb[(size_t)(2 * kp + 1) * NPOS + n];
        sB[n * SW + kp] = pack_bf16x2(f0, f1);
    }
    // Crossed norms: sx indexed by row i, sy indexed by col j.
    if (tid < TM) {
        s_sxRow[tid] = g_sx[b * NPOS + m0 + tid];
    } else if (tid < TM + TN) {
        s_syCol[tid - TM] = g_sy[b * NPOS + n0 + (tid - TM)];
    }
    __syncthreads();

    // ---- per-thread base pointers; all inner offsets are immediates ----
    const uint32_t* pA = sA + (wm * 32 + qid) * SW + qtr;
    const uint32_t* pB = sB + (wn * 32 + qid) * SW + qtr;

    float acc[2][4][4];
#pragma unroll
    for (int mi = 0; mi < 2; mi++)
#pragma unroll
        for (int j = 0; j < 4; j++)
#pragma unroll
            for (int r = 0; r < 4; r++) acc[mi][j][r] = 0.f;

    // ---- main loop: 8 k-steps of K=16 ----
#pragma unroll
    for (int s = 0; s < 8; s++) {
        uint32_t af[2][4];
#pragma unroll
        for (int mi = 0; mi < 2; mi++) {
            af[mi][0] = pA[(mi * 16 + 0) * SW + s * 8];       // row g,   kp qtr
            af[mi][1] = pA[(mi * 16 + 8) * SW + s * 8];       // row g+8, kp qtr
            af[mi][2] = pA[(mi * 16 + 0) * SW + s * 8 + 4];   // row g,   kp qtr+4
            af[mi][3] = pA[(mi * 16 + 8) * SW + s * 8 + 4];   // row g+8, kp qtr+4
        }
#pragma unroll
        for (int j = 0; j < 4; j++) {
            uint32_t b0 = pB[j * 8 * SW + s * 8];
            uint32_t b1 = pB[j * 8 * SW + s * 8 + 4];
#pragma unroll
            for (int mi = 0; mi < 2; mi++) {
                mma_bf16(acc[mi][j][0], acc[mi][j][1], acc[mi][j][2], acc[mi][j][3],
                         af[mi][0], af[mi][1], af[mi][2], af[mi][3], b0, b1);
            }
        }
    }

    // ---- fused epilogue: P = sx[i] + sy[j] - 2*acc, float2 stores ----
#pragma unroll
    for (int mi = 0; mi < 2; mi++) {
#pragma unroll
        for (int h = 0; h < 2; h++) {
            int r = wm * 32 + mi * 16 + h * 8 + qid;
            float sxv = s_sxRow[r];
            size_t rowOff = ((size_t)b * NPOS + m0 + r) * (size_t)NPOS + n0;
#pragma unroll
            for (int j = 0; j < 4; j++) {
                int cb = wn * 32 + 8 * j + 2 * qtr;
                float d0 = acc[mi][j][h * 2 + 0];
                float d1 = acc[mi][j][h * 2 + 1];
                float2 v;
                v.x = s_syCol[cb + 0] + fmaf(-2.f, d0, sxv);
                v.y = s_syCol[cb + 1] + fmaf(-2.f, d1, sxv);
                *reinterpret_cast<float2*>(out + rowOff + cb) = v;
            }
        }
    }
}

// ---------------------------------------------------------------------------
// Launch
// ---------------------------------------------------------------------------
extern "C" void kernel_launch(void* const* d_in, const int* in_sizes, int n_in,
                              void* d_out, int out_size) {
    const float* x = (const float*)d_in[0];
    const float* y = (const float*)d_in[1];
    float* out = (float*)d_out;

    // Kernel 1: squared norms
    int total = BATCH * NPOS;
    pwd_norms_kernel<<<(total + 255) / 256, 256>>>(x, y);

    // Kernel 2: tiled bf16 GEMM + fused epilogue
    int smemBytes = ((TM + TN) * SW + TM + TN) * 4;   // ~52 KB
    cudaFuncSetAttribute(pwd_gemm_kernel,
                         cudaFuncAttributeMaxDynamicSharedMemorySize, smemBytes);
    dim3 grid(MT_N, MT_M, BATCH);
    pwd_gemm_kernel<<<grid, 256, smemBytes>>>(x, y, out);
}

// round 10
// speedup vs baseline: 2.0185x; 1.3455x over previous
#include <cuda_runtime.h>
#include <cuda_bf16.h>
#include <cstdint>

// Problem constants
#define BATCH 8
#define CDIM  128
#define NPOS  2304              // H*W = 48*48
#define TM    256               // CTA tile M (y rows)
#define TN    128               // CTA tile N (x cols)
#define MT_M  (NPOS / TM)       // 9
#define MT_N  (NPOS / TN)       // 18
#define SW    68                // SMEM row stride in 32-bit words (64 + 4 pad)
#define NTHREADS 512

// ---------------------------------------------------------------------------
// Scratch for squared norms (device globals — no allocation in kernel_launch)
// ---------------------------------------------------------------------------
__device__ float g_sx[BATCH * NPOS];
__device__ float g_sy[BATCH * NPOS];

// ---------------------------------------------------------------------------
// Kernel 1: per-position squared norms   sx[b,n] = sum_c x[b,c,n]^2  (fp32 exact)
// ---------------------------------------------------------------------------
__global__ void pwd_norms_kernel(const float* __restrict__ x,
                                 const float* __restrict__ y) {
    int idx = blockIdx.x * blockDim.x + threadIdx.x;
    if (idx >= BATCH * NPOS) return;
    int b = idx / NPOS;
    int n = idx - b * NPOS;
    const float* xp = x + (size_t)b * CDIM * NPOS + n;
    const float* yp = y + (size_t)b * CDIM * NPOS + n;
    float sx = 0.f, sy = 0.f;
#pragma unroll 8
    for (int c = 0; c < CDIM; c++) {
        float xv = xp[(size_t)c * NPOS];
        float yv = yp[(size_t)c * NPOS];
        sx = fmaf(xv, xv, sx);
        sy = fmaf(yv, yv, sy);
    }
    g_sx[idx] = sx;
    g_sy[idx] = sy;
}

// ---------------------------------------------------------------------------
// bf16 warp MMA (sm_80+ PTX): D(16x8,f32) += A(16x16,bf16) * B(16x8,bf16)
// ---------------------------------------------------------------------------
__device__ __forceinline__ void mma_bf16(
    float& d0, float& d1, float& d2, float& d3,
    uint32_t a0, uint32_t a1, uint32_t a2, uint32_t a3,
    uint32_t b0, uint32_t b1)
{
    asm volatile(
        "mma.sync.aligned.m16n8k16.row.col.f32.bf16.bf16.f32 "
        "{%0,%1,%2,%3}, {%4,%5,%6,%7}, {%8,%9}, {%0,%1,%2,%3};"
        : "+f"(d0), "+f"(d1), "+f"(d2), "+f"(d3)
        : "r"(a0), "r"(a1), "r"(a2), "r"(a3), "r"(b0), "r"(b1));
}

__device__ __forceinline__ uint32_t pack_bf16x2(float lo, float hi) {
    __nv_bfloat162 p = __floats2bfloat162_rn(lo, hi);   // .x = lo (lower k)
    return *reinterpret_cast<uint32_t*>(&p);
}

// ---------------------------------------------------------------------------
// Kernel 2: bf16 mma.sync GEMM, CTA tile 256x128, 16 warps of 64x32
//   acc[m][n] = y_i . x_j   (i = m0+m row, j = n0+n col)
//   out[b,i,j] = sx[i] + sy[j] - 2 * acc   (crossed norms per reference)
//
// SMEM rows hold 64 bf16x2 words (k-pairs), stride SW=68 words.
// Fragment LDS bank = (4*qid + qtr) mod 32 -> conflict-free.
// Staging STS bank  = (4*plo + klo) mod 32 -> conflict-free.
// ---------------------------------------------------------------------------
__global__ __launch_bounds__(NTHREADS, 1)
void pwd_gemm_kernel(const float* __restrict__ x,
                     const float* __restrict__ y,
                     float* __restrict__ out) {
    extern __shared__ uint32_t dsm[];
    uint32_t* sA = dsm;                            // 256 * 68 words
    uint32_t* sB = dsm + TM * SW;                  // 128 * 68 words
    float* s_sxRow = (float*)(dsm + (TM + TN) * SW);   // 256 floats
    float* s_syCol = s_sxRow + TM;                     // 128 floats

    int tid  = threadIdx.x;
    int lane = tid & 31;
    int w    = tid >> 5;
    int qid  = lane >> 2;   // 0..7
    int qtr  = lane & 3;    // 0..3
    int wm   = w >> 2;      // warp row 0..3 (64 rows each)
    int wn   = w & 3;       // warp col 0..3 (32 cols each)

    int n0 = blockIdx.x * TN;
    int m0 = blockIdx.y * TM;
    int b  = blockIdx.z;

    const float* yb = y + (size_t)b * CDIM * NPOS + m0;
    const float* xb = x + (size_t)b * CDIM * NPOS + n0;

    // ---- stage tiles: gmem [k][pos] fp32 -> smem [pos][kp] bf16x2 ----
    // lane map: plo = tid&7 (pos low), klo = (tid>>3)&3 (k-pair low)
    int plo = tid & 7;
    int klo = (tid >> 3) & 3;
    int w5  = tid >> 5;     // 0..15

    // A: 256 pos x 64 kp = 16384 words = 512 thr * 32
#pragma unroll
    for (int i = 0; i < 32; i++) {
        int hi = i * 16 + w5;              // 0..511
        int m  = plo | ((hi & 31) << 3);   // 0..255
        int kp = klo | ((hi >> 5) << 2);   // 0..63
        float f0 = yb[(size_t)(2 * kp) * NPOS + m];
        float f1 = yb[(size_t)(2 * kp + 1) * NPOS + m];
        sA[m * SW + kp] = pack_bf16x2(f0, f1);
    }
    // B: 128 pos x 64 kp = 8192 words = 512 thr * 16
#pragma unroll
    for (int i = 0; i < 16; i++) {
        int hi = i * 16 + w5;              // 0..255
        int n  = plo | ((hi & 15) << 3);   // 0..127
        int kp = klo | ((hi >> 4) << 2);   // 0..63
        float f0 = xb[(size_t)(2 * kp) * NPOS + n];
        float f1 = xb[(size_t)(2 * kp + 1) * NPOS + n];
        sB[n * SW + kp] = pack_bf16x2(f0, f1);
    }
    // Crossed norms: sx indexed by row i, sy indexed by col j.
    if (tid < TM) {
        s_sxRow[tid] = g_sx[b * NPOS + m0 + tid];
    } else if (tid < TM + TN) {
        s_syCol[tid - TM] = g_sy[b * NPOS + n0 + (tid - TM)];
    }
    __syncthreads();

    // ---- per-thread base pointers; all inner offsets are immediates ----
    const uint32_t* pA = sA + (wm * 64 + qid) * SW + qtr;
    const uint32_t* pB = sB + (wn * 32 + qid) * SW + qtr;

    float acc[4][4][4];
#pragma unroll
    for (int mi = 0; mi < 4; mi++)
#pragma unroll
        for (int j = 0; j < 4; j++)
#pragma unroll
            for (int r = 0; r < 4; r++) acc[mi][j][r] = 0.f;

    // ---- main loop: 8 k-steps of K=16; 24 LDS + 16 MMA per step ----
#pragma unroll
    for (int s = 0; s < 8; s++) {
        uint32_t af[4][4];
#pragma unroll
        for (int mi = 0; mi < 4; mi++) {
            af[mi][0] = pA[(mi * 16 + 0) * SW + s * 8];
            af[mi][1] = pA[(mi * 16 + 8) * SW + s * 8];
            af[mi][2] = pA[(mi * 16 + 0) * SW + s * 8 + 4];
            af[mi][3] = pA[(mi * 16 + 8) * SW + s * 8 + 4];
        }
#pragma unroll
        for (int j = 0; j < 4; j++) {
            uint32_t b0 = pB[j * 8 * SW + s * 8];
            uint32_t b1 = pB[j * 8 * SW + s * 8 + 4];
#pragma unroll
            for (int mi = 0; mi < 4; mi++) {
                mma_bf16(acc[mi][j][0], acc[mi][j][1], acc[mi][j][2], acc[mi][j][3],
                         af[mi][0], af[mi][1], af[mi][2], af[mi][3], b0, b1);
            }
        }
    }

    // ---- fused epilogue: P = sx[i] + sy[j] - 2*acc, float2 stores ----
#pragma unroll
    for (int mi = 0; mi < 4; mi++) {
#pragma unroll
        for (int h = 0; h < 2; h++) {
            int r = wm * 64 + mi * 16 + h * 8 + qid;
            float sxv = s_sxRow[r];
            size_t rowOff = ((size_t)b * NPOS + m0 + r) * (size_t)NPOS + n0;
#pragma unroll
            for (int j = 0; j < 4; j++) {
                int cb = wn * 32 + 8 * j + 2 * qtr;
                float d0 = acc[mi][j][h * 2 + 0];
                float d1 = acc[mi][j][h * 2 + 1];
                float2 v;
                v.x = s_syCol[cb + 0] + fmaf(-2.f, d0, sxv);
                v.y = s_syCol[cb + 1] + fmaf(-2.f, d1, sxv);
                *reinterpret_cast<float2*>(out + rowOff + cb) = v;
            }
        }
    }
}

// ---------------------------------------------------------------------------
// Launch
// ---------------------------------------------------------------------------
extern "C" void kernel_launch(void* const* d_in, const int* in_sizes, int n_in,
                              void* d_out, int out_size) {
    const float* x = (const float*)d_in[0];
    const float* y = (const float*)d_in[1];
    float* out = (float*)d_out;

    // Kernel 1: squared norms
    int total = BATCH * NPOS;
    pwd_norms_kernel<<<(total + 255) / 256, 256>>>(x, y);

    // Kernel 2: tiled bf16 GEMM + fused epilogue
    int smemBytes = ((TM + TN) * SW + TM + TN) * 4;   // ~106 KB
    cudaFuncSetAttribute(pwd_gemm_kernel,
                         cudaFuncAttributeMaxDynamicSharedMemorySize, smemBytes);
    dim3 grid(MT_N, MT_M, BATCH);
    pwd_gemm_kernel<<<grid, NTHREADS, smemBytes>>>(x, y, out);
}

// round 11
// speedup vs baseline: 2.3931x; 1.1856x over previous
#include <cuda_runtime.h>
#include <cuda_bf16.h>
#include <cstdint>

// Problem constants
#define BATCH 8
#define CDIM  128
#define NPOS  2304              // H*W = 48*48
#define TM    256               // CTA tile M (y rows)
#define TN    128               // CTA tile N (x cols)
#define NL    3                 // n-tiles per CTA (A reused across them)
#define MT_M  (NPOS / TM)       // 9
#define MT_NS (NPOS / (TN*NL))  // 6 n-strips
#define SW    68                // SMEM row stride in 32-bit words (64 + 4 pad)
#define NTHREADS 512

// ---------------------------------------------------------------------------
// Scratch for squared norms (device globals — no allocation in kernel_launch)
// ---------------------------------------------------------------------------
__device__ float g_sx[BATCH * NPOS];
__device__ float g_sy[BATCH * NPOS];

// ---------------------------------------------------------------------------
// Kernel 1: per-position squared norms   sx[b,n] = sum_c x[b,c,n]^2  (fp32 exact)
// ---------------------------------------------------------------------------
__global__ void pwd_norms_kernel(const float* __restrict__ x,
                                 const float* __restrict__ y) {
    int idx = blockIdx.x * blockDim.x + threadIdx.x;
    if (idx >= BATCH * NPOS) return;
    int b = idx / NPOS;
    int n = idx - b * NPOS;
    const float* xp = x + (size_t)b * CDIM * NPOS + n;
    const float* yp = y + (size_t)b * CDIM * NPOS + n;
    float sx = 0.f, sy = 0.f;
#pragma unroll 8
    for (int c = 0; c < CDIM; c++) {
        float xv = xp[(size_t)c * NPOS];
        float yv = yp[(size_t)c * NPOS];
        sx = fmaf(xv, xv, sx);
        sy = fmaf(yv, yv, sy);
    }
    g_sx[idx] = sx;
    g_sy[idx] = sy;
}

// ---------------------------------------------------------------------------
// bf16 warp MMA (sm_80+ PTX): D(16x8,f32) += A(16x16,bf16) * B(16x8,bf16)
// ---------------------------------------------------------------------------
__device__ __forceinline__ void mma_bf16(
    float& d0, float& d1, float& d2, float& d3,
    uint32_t a0, uint32_t a1, uint32_t a2, uint32_t a3,
    uint32_t b0, uint32_t b1)
{
    asm volatile(
        "mma.sync.aligned.m16n8k16.row.col.f32.bf16.bf16.f32 "
        "{%0,%1,%2,%3}, {%4,%5,%6,%7}, {%8,%9}, {%0,%1,%2,%3};"
        : "+f"(d0), "+f"(d1), "+f"(d2), "+f"(d3)
        : "r"(a0), "r"(a1), "r"(a2), "r"(a3), "r"(b0), "r"(b1));
}

__device__ __forceinline__ uint32_t pack_bf16x2(float lo, float hi) {
    __nv_bfloat162 p = __floats2bfloat162_rn(lo, hi);   // .x = lo (lower k)
    return *reinterpret_cast<uint32_t*>(&p);
}

// ---------------------------------------------------------------------------
// Kernel 2: bf16 mma.sync GEMM, CTA tile 256x128, A reused over NL=3 n-tiles.
//   acc[m][n] = y_i . x_j   (i = m0+m row, j = n0+n col)
//   out[b,i,j] = sx[i] + sy[j] - 2 * acc   (crossed norms per reference)
// ---------------------------------------------------------------------------
__global__ __launch_bounds__(NTHREADS, 1)
void pwd_gemm_kernel(const float* __restrict__ x,
                     const float* __restrict__ y,
                     float* __restrict__ out) {
    extern __shared__ uint32_t dsm[];
    uint32_t* sA = dsm;                            // 256 * 68 words
    uint32_t* sB = dsm + TM * SW;                  // 128 * 68 words
    float* s_sxRow = (float*)(dsm + (TM + TN) * SW);   // 256 floats
    float* s_syCol = s_sxRow + TM;                     // 128 floats

    int tid  = threadIdx.x;
    int lane = tid & 31;
    int w    = tid >> 5;
    int qid  = lane >> 2;   // 0..7
    int qtr  = lane & 3;    // 0..3
    int wm   = w >> 2;      // warp row 0..3 (64 rows each)
    int wn   = w & 3;       // warp col 0..3 (32 cols each)

    int m0 = blockIdx.y * TM;
    int b  = blockIdx.z;

    const float* yb = y + (size_t)b * CDIM * NPOS + m0;

    // lane map: plo = tid&7 (pos low), klo = (tid>>3)&3 (k-pair low)
    int plo = tid & 7;
    int klo = (tid >> 3) & 3;
    int w5  = tid >> 5;     // 0..15

    // ---- stage A once: 256 pos x 64 kp ----
#pragma unroll
    for (int i = 0; i < 32; i++) {
        int hi = i * 16 + w5;              // 0..511
        int m  = plo | ((hi & 31) << 3);   // 0..255
        int kp = klo | ((hi >> 5) << 2);   // 0..63
        float f0 = yb[(size_t)(2 * kp) * NPOS + m];
        float f1 = yb[(size_t)(2 * kp + 1) * NPOS + m];
        sA[m * SW + kp] = pack_bf16x2(f0, f1);
    }
    if (tid < TM) {
        s_sxRow[tid] = g_sx[b * NPOS + m0 + tid];
    }

    // per-thread base pointers (constant across n-tiles)
    const uint32_t* pA = sA + (wm * 64 + qid) * SW + qtr;
    const uint32_t* pB = sB + (wn * 32 + qid) * SW + qtr;

    // ---- loop over NL n-tiles sharing this A ----
    for (int t = 0; t < NL; t++) {
        int n0 = (blockIdx.x * NL + t) * TN;
        const float* xb = x + (size_t)b * CDIM * NPOS + n0;

        // stage B tile: 128 pos x 64 kp  (prev tile's compute done: sync below)
#pragma unroll
        for (int i = 0; i < 16; i++) {
            int hi = i * 16 + w5;              // 0..255
            int n  = plo | ((hi & 15) << 3);   // 0..127
            int kp = klo | ((hi >> 4) << 2);   // 0..63
            float f0 = xb[(size_t)(2 * kp) * NPOS + n];
            float f1 = xb[(size_t)(2 * kp + 1) * NPOS + n];
            sB[n * SW + kp] = pack_bf16x2(f0, f1);
        }
        if (tid >= TM && tid < TM + TN) {
            s_syCol[tid - TM] = g_sy[b * NPOS + n0 + (tid - TM)];
        }
        __syncthreads();

        float acc[4][4][4];
#pragma unroll
        for (int mi = 0; mi < 4; mi++)
#pragma unroll
            for (int j = 0; j < 4; j++)
#pragma unroll
                for (int r = 0; r < 4; r++) acc[mi][j][r] = 0.f;

        // main loop: 8 k-steps of K=16; 24 LDS + 16 MMA per step
#pragma unroll
        for (int s = 0; s < 8; s++) {
            uint32_t af[4][4];
#pragma unroll
            for (int mi = 0; mi < 4; mi++) {
                af[mi][0] = pA[(mi * 16 + 0) * SW + s * 8];
                af[mi][1] = pA[(mi * 16 + 8) * SW + s * 8];
                af[mi][2] = pA[(mi * 16 + 0) * SW + s * 8 + 4];
                af[mi][3] = pA[(mi * 16 + 8) * SW + s * 8 + 4];
            }
#pragma unroll
            for (int j = 0; j < 4; j++) {
                uint32_t b0 = pB[j * 8 * SW + s * 8];
                uint32_t b1 = pB[j * 8 * SW + s * 8 + 4];
#pragma unroll
                for (int mi = 0; mi < 4; mi++) {
                    mma_bf16(acc[mi][j][0], acc[mi][j][1], acc[mi][j][2], acc[mi][j][3],
                             af[mi][0], af[mi][1], af[mi][2], af[mi][3], b0, b1);
                }
            }
        }

        // fused epilogue: P = sx[i] + sy[j] - 2*acc, float2 stores
#pragma unroll
        for (int mi = 0; mi < 4; mi++) {
#pragma unroll
            for (int h = 0; h < 2; h++) {
                int r = wm * 64 + mi * 16 + h * 8 + qid;
                float sxv = s_sxRow[r];
                size_t rowOff = ((size_t)b * NPOS + m0 + r) * (size_t)NPOS + n0;
#pragma unroll
                for (int j = 0; j < 4; j++) {
                    int cb = wn * 32 + 8 * j + 2 * qtr;
                    float d0 = acc[mi][j][h * 2 + 0];
                    float d1 = acc[mi][j][h * 2 + 1];
                    float2 v;
                    v.x = s_syCol[cb + 0] + fmaf(-2.f, d0, sxv);
                    v.y = s_syCol[cb + 1] + fmaf(-2.f, d1, sxv);
                    *reinterpret_cast<float2*>(out + rowOff + cb) = v;
                }
            }
        }
        __syncthreads();   // protect sB / s_syCol before next tile's staging
    }
}

// ---------------------------------------------------------------------------
// Launch
// ---------------------------------------------------------------------------
extern "C" void kernel_launch(void* const* d_in, const int* in_sizes, int n_in,
                              void* d_out, int out_size) {
    const float* x = (const float*)d_in[0];
    const float* y = (const float*)d_in[1];
    float* out = (float*)d_out;

    // Kernel 1: squared norms
    int total = BATCH * NPOS;
    pwd_norms_kernel<<<(total + 255) / 256, 256>>>(x, y);

    // Kernel 2: tiled bf16 GEMM + fused epilogue, A reused over n-strip
    int smemBytes = ((TM + TN) * SW + TM + TN) * 4;   // ~106 KB
    cudaFuncSetAttribute(pwd_gemm_kernel,
                         cudaFuncAttributeMaxDynamicSharedMemorySize, smemBytes);
    dim3 grid(MT_NS, MT_M, BATCH);
    pwd_gemm_kernel<<<grid, NTHREADS, smemBytes>>>(x, y, out);
}